// round 16
// baseline (speedup 1.0000x reference)
#include <cuda_runtime.h>
#include <cstdint>

#define NF 4096
#define D 128
#define NBINS 101
#define NB2 (2 * NBINS)
#define TT 64             // CTA tile (square)
#define KST 132           // smem row stride in floats (528B; 132 mod 32 = 4 banks)
#define THREADS 256
#define NHCOPY 2
#define NTILE (NF / TT)   // 64
#define NBLK (NTILE * (NTILE + 1) / 2)   // 2080
#define QSCALE 262144.0f
#define QMASK ((1ULL << 40) - 1ULL)

__device__ float g_cnt[NB2];            // zero at load; last CTA re-zeroes per run
__device__ float g_frc[NB2];
__device__ unsigned int g_done = 0;     // last-CTA turnstile; reset by last CTA

#define FMA2(d, a, b) \
    asm("fma.rn.f32x2 %0, %1, %2, %0;" : "+l"(d) : "l"(a), "l"(b))

__device__ __forceinline__ uint32_t smem_to_u32(const void* p) {
    uint32_t a;
    asm("{ .reg .u64 t; cvta.to.shared.u64 t, %1; cvt.u32.u64 %0, t; }" : "=r"(a) : "l"(p));
    return a;
}
#define CP_ASYNC16(sa, ga) \
    asm volatile("cp.async.ca.shared.global [%0], [%1], 16;" :: "r"(sa), "l"(ga) : "memory")

__global__ __launch_bounds__(THREADS, 3)
void pair_hist_kernel(const float* __restrict__ F, const void* __restrict__ cls_raw,
                      float* __restrict__ out) {
    // linear triangular decode: blockIdx.x in [0, NBLK)
    const int L = blockIdx.x;
    int u = (NBLK - 1) - L;
    int r = (int)((sqrtf(8.0f * (float)u + 1.0f) - 1.0f) * 0.5f);
    while ((r + 1) * (r + 2) / 2 <= u) r++;
    while (r * (r + 1) / 2 > u) r--;
    const int bi = (NTILE - 1) - r;
    const int bj = (NTILE - 1) - (u - r * (r + 1) / 2);

    extern __shared__ __align__(16) float dsm[];
    float* As = dsm;                       // 64 x 132
    float* Bs = dsm + TT * KST;            // 64 x 132
    __shared__ unsigned long long whist[NHCOPY][NB2];
    __shared__ int clsA[TT], clsB[TT];

    const int t    = threadIdx.x;
    const int wid  = t >> 5;
    const int lane = t & 31;
    const int idxR = (lane & 7) + 8 * (wid & 1);
    const int idxC = (lane >> 3) + 4 * (wid >> 1);

    const uint32_t sA = smem_to_u32(As);
    const uint32_t sB = smem_to_u32(Bs);
    const float* Arow = F + (size_t)bi * TT * D;
    const float* Brow = F + (size_t)bj * TT * D;

    // async-load both full-K tiles: 64 rows x 32 float4 slots each
#pragma unroll
    for (int it = 0; it < 8; it++) {
        int s = it * THREADS + t;
        int rr = s >> 5, q = s & 31;
        uint32_t soff = (uint32_t)(rr * KST + q * 4) * 4u;
        CP_ASYNC16(sA + soff, Arow + rr * D + q * 4);
        CP_ASYNC16(sB + soff, Brow + rr * D + q * 4);
    }
    asm volatile("cp.async.commit_group;" ::: "memory");

    for (int i = t; i < NHCOPY * NB2; i += THREADS) (&whist[0][0])[i] = 0ULL;

    // inline dtype sniff: int64 classes (LE) have zero odd words (classes 0..31)
    const int* c32 = (const int*)cls_raw;
    const bool is64 = ((c32[1] | c32[3] | c32[5] | c32[7]) == 0);

    if (t < TT) {
        int va, vb;
        if (is64) {
            va = (int)((const long long*)cls_raw)[bi * TT + t];
            vb = (int)((const long long*)cls_raw)[bj * TT + t];
        } else {
            va = c32[bi * TT + t];
            vb = c32[bj * TT + t];
        }
        clsA[t] = va; clsB[t] = vb;
    }

    unsigned long long acc[4][4];
#pragma unroll
    for (int m = 0; m < 4; m++)
#pragma unroll
        for (int n = 0; n < 4; n++) acc[m][n] = 0ULL;

    asm volatile("cp.async.wait_group 0;" ::: "memory");
    __syncthreads();

    const float* Abase = As + idxR * KST;
    const float* Bbase = Bs + idxC * KST;
#pragma unroll
    for (int kk = 0; kk < D / 4; kk++) {
        ulonglong2 a2[4], b2[4];
#pragma unroll
        for (int m = 0; m < 4; m++)
            a2[m] = *reinterpret_cast<const ulonglong2*>(Abase + m * 16 * KST + 4 * kk);
#pragma unroll
        for (int n = 0; n < 4; n++)
            b2[n] = *reinterpret_cast<const ulonglong2*>(Bbase + n * 16 * KST + 4 * kk);
#pragma unroll
        for (int m = 0; m < 4; m++)
#pragma unroll
            for (int n = 0; n < 4; n++) {
                FMA2(acc[m][n], a2[m].x, b2[n].x);
                FMA2(acc[m][n], a2[m].y, b2[n].y);
            }
    }

    // ---- warp-aggregated binning ----
    unsigned long long* hw = whist[wid & (NHCOPY - 1)];
    const int dj = (bj - bi) * TT;
#pragma unroll
    for (int m = 0; m < 4; m++) {
        const int il = idxR + 16 * m;
        const int ci = clsA[il];
#pragma unroll
        for (int n = 0; n < 4; n++) {
            const int jl = idxC + 16 * n;
            const bool valid = (jl + dj) > il;
            float lo, hi;
            asm("mov.b64 {%0, %1}, %2;" : "=f"(lo), "=f"(hi) : "l"(acc[m][n]));
            float s = lo + hi;
            float posf = fmaf(s, 50.0f, 50.0f);
            int idx = (int)floorf(posf);
            idx = max(0, min(idx, NBINS - 1));
            float frac = posf - (float)idx;
            frac = fminf(fmaxf(frac, 0.0f), 1.0f);
            int key = idx + ((ci == clsB[jl]) ? 0 : NBINS);
            unsigned q = __float2uint_rn(frac * QSCALE);
            unsigned act = __ballot_sync(0xffffffffu, valid);
            if (valid) {
                unsigned grp = __match_any_sync(act, key);
                unsigned qs  = __reduce_add_sync(grp, q);
                if (lane == __ffs(grp) - 1) {
                    unsigned long long v =
                        ((unsigned long long)__popc(grp) << 40) | (unsigned long long)qs;
                    atomicAdd(&hw[key], v);
                }
            }
        }
    }

    __syncthreads();
    for (int i = t; i < NB2; i += THREADS) {
        unsigned long long s = 0ULL;
#pragma unroll
        for (int w = 0; w < NHCOPY; w++) s += whist[w][i];
        if (s != 0ULL) {
            atomicAdd(&g_cnt[i], (float)(unsigned)(s >> 40));
            atomicAdd(&g_frc[i], (float)(unsigned long long)(s & QMASK) * (1.0f / QSCALE));
        }
    }

    // ---- last-CTA fused finalize ----
    __shared__ bool amLast;
    __threadfence();
    __syncthreads();
    if (t == 0) {
        unsigned v = atomicAdd(&g_done, 1u);
        amLast = (v == NBLK - 1);
        if (amLast) g_done = 0;          // reset for next graph replay
    }
    __syncthreads();
    if (!amLast) return;
    __threadfence();                      // acquire: see all CTAs' g_cnt/g_frc

    __shared__ double scanp[NBINS];      // inclusive CDF of hp
    __shared__ double redp[NBINS];       // reduction scratch (Sn, loss)
    __shared__ float hns[NBINS];

    if (t < NB2) {
        int b = (t < NBINS) ? t : (t - NBINS);
        float h = g_cnt[t];
        if (b < NBINS - 1) h -= g_frc[t];
        if (b > 0)         h += g_frc[t - 1];
        if (t < NBINS) scanp[b] = (double)h;
        else           hns[b]   = h;
        g_cnt[t] = 0.0f;                  // self-restore for replay
        g_frc[t] = 0.0f;
    }
    __syncthreads();

    // Hillis-Steele inclusive scan over NBINS doubles
#pragma unroll
    for (int off = 1; off < 128; off <<= 1) {
        double v = 0.0;
        if (t < NBINS && t >= off) v = scanp[t - off];
        __syncthreads();
        if (t < NBINS && t >= off) scanp[t] += v;
        __syncthreads();
    }

    // Sn and loss partials
    if (t < NBINS) redp[t] = (double)hns[t];
    __syncthreads();
    // tree-reduce Sn into redp[0]
#pragma unroll
    for (int off = 64; off >= 1; off >>= 1) {
        if (t < off && t + off < NBINS) redp[t] += redp[t + off];
        __syncthreads();
    }
    __shared__ double Sn_sh;
    if (t == 0) Sn_sh = redp[0];
    __syncthreads();

    if (t < NBINS) redp[t] = (double)hns[t] * scanp[t];
    __syncthreads();
#pragma unroll
    for (int off = 64; off >= 1; off >>= 1) {
        if (t < off && t + off < NBINS) redp[t] += redp[t + off];
        __syncthreads();
    }
    if (t == 0) {
        double Sp = scanp[NBINS - 1];
        double Sn = Sn_sh;
        if (Sp <= 0.0) Sp = 1.0;
        if (Sn <= 0.0) Sn = 1.0;
        out[0] = (float)(redp[0] / (Sp * Sn));
    }
}

extern "C" void kernel_launch(void* const* d_in, const int* in_sizes, int n_in,
                              void* d_out, int out_size) {
    const float* F  = (const float*)d_in[0];
    const void* cls = d_in[1];
    (void)in_sizes; (void)n_in; (void)out_size;

    const int DSMEM = 2 * TT * KST * 4;   // 67584 bytes
    cudaFuncSetAttribute(pair_hist_kernel, cudaFuncAttributeMaxDynamicSharedMemorySize, DSMEM);

    pair_hist_kernel<<<NBLK, THREADS, DSMEM>>>(F, cls, (float*)d_out);
}

// round 17
// speedup vs baseline: 1.6491x; 1.6491x over previous
#include <cuda_runtime.h>
#include <cstdint>

#define NF 4096
#define D 128
#define NBINS 101
#define NB2 (2 * NBINS)
#define TT 64             // CTA tile (square)
#define KST 132           // smem row stride in floats (528B; 132 mod 32 = 4 banks)
#define THREADS 256
#define NHCOPY 2
#define NTILE (NF / TT)   // 64
#define NBLK (NTILE * (NTILE + 1) / 2)   // 2080
#define QSCALE 262144.0f
#define QMASK ((1ULL << 40) - 1ULL)

__device__ float g_cnt[NB2];   // zero at load; finalize re-zeroes after each run
__device__ float g_frc[NB2];

#define FMA2(d, a, b) \
    asm("fma.rn.f32x2 %0, %1, %2, %0;" : "+l"(d) : "l"(a), "l"(b))

__device__ __forceinline__ uint32_t smem_to_u32(const void* p) {
    uint32_t a;
    asm("{ .reg .u64 t; cvta.to.shared.u64 t, %1; cvt.u32.u64 %0, t; }" : "=r"(a) : "l"(p));
    return a;
}
#define CP_ASYNC16(sa, ga) \
    asm volatile("cp.async.ca.shared.global [%0], [%1], 16;" :: "r"(sa), "l"(ga) : "memory")

__global__ __launch_bounds__(THREADS, 3)
void pair_hist_kernel(const float* __restrict__ F, const void* __restrict__ cls_raw) {
    // linear triangular decode: blockIdx.x in [0, NBLK)
    const int L = blockIdx.x;
    int u = (NBLK - 1) - L;
    int r = (int)((sqrtf(8.0f * (float)u + 1.0f) - 1.0f) * 0.5f);
    while ((r + 1) * (r + 2) / 2 <= u) r++;
    while (r * (r + 1) / 2 > u) r--;
    const int bi = (NTILE - 1) - r;
    const int bj = (NTILE - 1) - (u - r * (r + 1) / 2);

    extern __shared__ __align__(16) float dsm[];
    float* As = dsm;                       // 64 x 132
    float* Bs = dsm + TT * KST;            // 64 x 132
    __shared__ unsigned long long whist[NHCOPY][NB2];
    __shared__ int clsA[TT], clsB[TT];

    const int t    = threadIdx.x;
    const int wid  = t >> 5;
    const int lane = t & 31;
    const int idxR = (lane & 7) + 8 * (wid & 1);
    const int idxC = (lane >> 3) + 4 * (wid >> 1);

    const uint32_t sA = smem_to_u32(As);
    const uint32_t sB = smem_to_u32(Bs);
    const float* Arow = F + (size_t)bi * TT * D;
    const float* Brow = F + (size_t)bj * TT * D;

    // async-load both full-K tiles: 64 rows x 32 float4 slots each
#pragma unroll
    for (int it = 0; it < 8; it++) {
        int s = it * THREADS + t;
        int rr = s >> 5, q = s & 31;
        uint32_t soff = (uint32_t)(rr * KST + q * 4) * 4u;
        CP_ASYNC16(sA + soff, Arow + rr * D + q * 4);
        CP_ASYNC16(sB + soff, Brow + rr * D + q * 4);
    }
    asm volatile("cp.async.commit_group;" ::: "memory");

    for (int i = t; i < NHCOPY * NB2; i += THREADS) (&whist[0][0])[i] = 0ULL;

    // inline dtype sniff: int64 classes (LE) have zero odd words (classes 0..31)
    const int* c32 = (const int*)cls_raw;
    const bool is64 = ((c32[1] | c32[3] | c32[5] | c32[7]) == 0);

    if (t < TT) {
        int va, vb;
        if (is64) {
            va = (int)((const long long*)cls_raw)[bi * TT + t];
            vb = (int)((const long long*)cls_raw)[bj * TT + t];
        } else {
            va = c32[bi * TT + t];
            vb = c32[bj * TT + t];
        }
        clsA[t] = va; clsB[t] = vb;
    }

    unsigned long long acc[4][4];
#pragma unroll
    for (int m = 0; m < 4; m++)
#pragma unroll
        for (int n = 0; n < 4; n++) acc[m][n] = 0ULL;

    asm volatile("cp.async.wait_group 0;" ::: "memory");
    __syncthreads();

    // fully-unrolled K loop: invariant bases + compile-time offsets
    const float* Abase = As + idxR * KST;
    const float* Bbase = Bs + idxC * KST;
#pragma unroll
    for (int kk = 0; kk < D / 4; kk++) {
        ulonglong2 a2[4], b2[4];
#pragma unroll
        for (int m = 0; m < 4; m++)
            a2[m] = *reinterpret_cast<const ulonglong2*>(Abase + m * 16 * KST + 4 * kk);
#pragma unroll
        for (int n = 0; n < 4; n++)
            b2[n] = *reinterpret_cast<const ulonglong2*>(Bbase + n * 16 * KST + 4 * kk);
#pragma unroll
        for (int m = 0; m < 4; m++)
#pragma unroll
            for (int n = 0; n < 4; n++) {
                FMA2(acc[m][n], a2[m].x, b2[n].x);
                FMA2(acc[m][n], a2[m].y, b2[n].y);
            }
    }

    // ---- warp-aggregated binning ----
    unsigned long long* hw = whist[wid & (NHCOPY - 1)];
    const int dj = (bj - bi) * TT;   // valid iff jl + dj > il
#pragma unroll
    for (int m = 0; m < 4; m++) {
        const int il = idxR + 16 * m;
        const int ci = clsA[il];
#pragma unroll
        for (int n = 0; n < 4; n++) {
            const int jl = idxC + 16 * n;
            const bool valid = (jl + dj) > il;
            float lo, hi;
            asm("mov.b64 {%0, %1}, %2;" : "=f"(lo), "=f"(hi) : "l"(acc[m][n]));
            float s = lo + hi;
            float posf = fmaf(s, 50.0f, 50.0f);     // (s+1)/step, step = 2/100
            int idx = (int)floorf(posf);
            idx = max(0, min(idx, NBINS - 1));
            float frac = posf - (float)idx;
            frac = fminf(fmaxf(frac, 0.0f), 1.0f);
            int key = idx + ((ci == clsB[jl]) ? 0 : NBINS);
            unsigned q = __float2uint_rn(frac * QSCALE);
            unsigned act = __ballot_sync(0xffffffffu, valid);
            if (valid) {
                unsigned grp = __match_any_sync(act, key);
                unsigned qs  = __reduce_add_sync(grp, q);
                if (lane == __ffs(grp) - 1) {
                    unsigned long long v =
                        ((unsigned long long)__popc(grp) << 40) | (unsigned long long)qs;
                    atomicAdd(&hw[key], v);
                }
            }
        }
    }

    __syncthreads();
    for (int i = t; i < NB2; i += THREADS) {
        unsigned long long s = 0ULL;
#pragma unroll
        for (int w = 0; w < NHCOPY; w++) s += whist[w][i];
        if (s != 0ULL) {
            atomicAdd(&g_cnt[i], (float)(unsigned)(s >> 40));
            atomicAdd(&g_frc[i], (float)(unsigned long long)(s & QMASK) * (1.0f / QSCALE));
        }
    }
}

__global__ void finalize_kernel(float* out) {
    __shared__ float scnt[NB2], sfrc[NB2];
    __shared__ float hns[NBINS];
    __shared__ double scanp[NBINS], redp[NBINS];
    __shared__ double Sn_sh;
    const int t = threadIdx.x;

    // stage to shared, THEN zero globals (race-free: cross-thread reads hit shared)
    if (t < NB2) {
        scnt[t] = g_cnt[t];
        sfrc[t] = g_frc[t];
        g_cnt[t] = 0.0f;     // self-restore for next graph replay
        g_frc[t] = 0.0f;
    }
    __syncthreads();

    if (t < NB2) {
        int b = (t < NBINS) ? t : (t - NBINS);
        float h = scnt[t];
        if (b < NBINS - 1) h -= sfrc[t];
        if (b > 0)         h += sfrc[t - 1];
        if (t < NBINS) scanp[b] = (double)h;
        else           hns[b]   = h;
    }
    __syncthreads();

    // Hillis-Steele inclusive scan over NBINS doubles (7 steps)
#pragma unroll
    for (int off = 1; off < 128; off <<= 1) {
        double v = 0.0;
        if (t < NBINS && t >= off) v = scanp[t - off];
        __syncthreads();
        if (t < NBINS && t >= off) scanp[t] += v;
        __syncthreads();
    }

    // Sn = sum(hn)
    if (t < NBINS) redp[t] = (double)hns[t];
    __syncthreads();
#pragma unroll
    for (int off = 64; off >= 1; off >>= 1) {
        if (t < off && t + off < NBINS) redp[t] += redp[t + off];
        __syncthreads();
    }
    if (t == 0) Sn_sh = redp[0];
    __syncthreads();

    // loss = sum(hn * cdf)
    if (t < NBINS) redp[t] = (double)hns[t] * scanp[t];
    __syncthreads();
#pragma unroll
    for (int off = 64; off >= 1; off >>= 1) {
        if (t < off && t + off < NBINS) redp[t] += redp[t + off];
        __syncthreads();
    }
    if (t == 0) {
        double Sp = scanp[NBINS - 1];
        double Sn = Sn_sh;
        if (Sp <= 0.0) Sp = 1.0;
        if (Sn <= 0.0) Sn = 1.0;
        out[0] = (float)(redp[0] / (Sp * Sn));
    }
}

extern "C" void kernel_launch(void* const* d_in, const int* in_sizes, int n_in,
                              void* d_out, int out_size) {
    const float* F  = (const float*)d_in[0];
    const void* cls = d_in[1];
    (void)in_sizes; (void)n_in; (void)out_size;

    const int DSMEM = 2 * TT * KST * 4;   // 67584 bytes
    cudaFuncSetAttribute(pair_hist_kernel, cudaFuncAttributeMaxDynamicSharedMemorySize, DSMEM);

    pair_hist_kernel<<<NBLK, THREADS, DSMEM>>>(F, cls);
    finalize_kernel<<<1, 256>>>((float*)d_out);
}